// round 1
// baseline (speedup 1.0000x reference)
#include <cuda_runtime.h>
#include <math.h>

#define Dd 128
#define Hh 512
#define Ww 512
#define OD 32
#define HW (Hh*Ww)
#define HW4 (HW/4)
#define INV_SQRT_2PI 0.3989422804014327f

// scratch: z-conv output (32,512,512) f32 = 33.5 MB
__device__ __align__(16) float g_tmp1[(size_t)OD * HW];
__device__ unsigned g_minb;
__device__ unsigned g_maxb;

// float -> order-preserving uint (monotone), and inverse
__device__ __forceinline__ unsigned f2o(float f) {
    unsigned u = __float_as_uint(f);
    return (u & 0x80000000u) ? ~u : (u | 0x80000000u);
}
__device__ __forceinline__ float o2f(unsigned u) {
    return (u & 0x80000000u) ? __uint_as_float(u ^ 0x80000000u)
                             : __uint_as_float(~u);
}

__global__ void k_init() {
    g_minb = 0xFFFFFFFFu;
    g_maxb = 0u;
}

// ---------------------------------------------------------------------------
// Kernel 1: strided z-conv.  Each thread handles one float4 (x,y) group and
// 8 consecutive output z-planes.  Reads 37 input planes, writes 8 outputs.
// out[zo] = sum_{kz=0..8} wz[kz] * in[4*zo - 3 + kz]
// ---------------------------------------------------------------------------
__global__ void __launch_bounds__(256) k_zconv(
    const float4* __restrict__ in,
    const float* __restrict__ p_mu, const float* __restrict__ p_sig,
    const float* __restrict__ p_bz)
{
    int idx = blockIdx.x * 256 + threadIdx.x;   // 0 .. HW4-1
    int zb  = blockIdx.y * 8;                   // first output z of this chunk

    float bz  = *p_bz;
    float z0  = expf(*p_mu + 0.5f * (*p_sig) * (*p_sig));
    float amp = INV_SQRT_2PI * z0;
    float inv2b2 = 1.0f / (2.0f * bz * bz);

    float wz[9];
#pragma unroll
    for (int k = 0; k < 9; k++) {
        float d = (float)(k - 4);
        wz[k] = expf(-d * d * inv2b2) * amp;
    }

    float4 acc[8];
#pragma unroll
    for (int j = 0; j < 8; j++) acc[j] = make_float4(0.f, 0.f, 0.f, 0.f);

    int base = 4 * zb - 3;
#pragma unroll
    for (int iz = 0; iz < 37; iz++) {
        int z = base + iz;
        float4 v;
        if (z >= 0 && z < Dd) v = in[(size_t)z * HW4 + idx];
        else                  v = make_float4(0.f, 0.f, 0.f, 0.f);
#pragma unroll
        for (int j = 0; j < 8; j++) {
            int kz = iz - 4 * j;            // compile-time per (iz,j)
            if (kz >= 0 && kz < 9) {
                float w = wz[kz];
                acc[j].x += w * v.x;
                acc[j].y += w * v.y;
                acc[j].z += w * v.z;
                acc[j].w += w * v.w;
            }
        }
    }

    float4* out = reinterpret_cast<float4*>(g_tmp1);
#pragma unroll
    for (int j = 0; j < 8; j++)
        out[(size_t)(zb + j) * HW4 + idx] = acc[j];
}

// ---------------------------------------------------------------------------
// Kernel 2: fused x-conv + y-conv on each of 32 planes, smem tiled 32x32
// (40x40 halo), with fused global min/max reduction.
// Writes conv result to d_out.
// ---------------------------------------------------------------------------
__global__ void __launch_bounds__(256) k_xyconv(
    const float* __restrict__ p_bxy, float* __restrict__ out)
{
    __shared__ float s_in[40 * 40];
    __shared__ float s_tmp[32 * 40];
    __shared__ float smin[8], smax[8];

    int z  = blockIdx.z;
    int X0 = blockIdx.y * 32;
    int Y0 = blockIdx.x * 32;
    int t  = threadIdx.x;

    float bxy = *p_bxy;
    float inv2b2 = 1.0f / (2.0f * bxy * bxy);
    float w[9];
#pragma unroll
    for (int k = 0; k < 9; k++) {
        float d = (float)(k - 4);
        w[k] = expf(-d * d * inv2b2);
    }

    const float* src = g_tmp1 + (size_t)z * HW;

    // load 40x40 halo (zero padded)
    for (int i = t; i < 1600; i += 256) {
        int r = i / 40, c = i % 40;
        int gx = X0 - 4 + r, gy = Y0 - 4 + c;
        s_in[i] = (gx >= 0 && gx < Hh && gy >= 0 && gy < Ww)
                      ? src[(size_t)gx * Ww + gy] : 0.f;
    }
    __syncthreads();

    // x-conv: 32 x 40
    for (int i = t; i < 1280; i += 256) {
        int x = i / 40, yy = i % 40;
        float s = 0.f;
#pragma unroll
        for (int k = 0; k < 9; k++) s += w[k] * s_in[(x + k) * 40 + yy];
        s_tmp[i] = s;
    }
    __syncthreads();

    // y-conv: 32 x 32, fused min/max
    float lmin =  3.402823466e38f;
    float lmax = -3.402823466e38f;
    for (int i = t; i < 1024; i += 256) {
        int x = i / 32, y = i % 32;
        float s = 0.f;
#pragma unroll
        for (int k = 0; k < 9; k++) s += w[k] * s_tmp[x * 40 + y + k];
        out[(size_t)z * HW + (size_t)(X0 + x) * Ww + (Y0 + y)] = s;
        lmin = fminf(lmin, s);
        lmax = fmaxf(lmax, s);
    }

    // warp reduce
#pragma unroll
    for (int o = 16; o > 0; o >>= 1) {
        lmin = fminf(lmin, __shfl_xor_sync(0xFFFFFFFFu, lmin, o));
        lmax = fmaxf(lmax, __shfl_xor_sync(0xFFFFFFFFu, lmax, o));
    }
    if ((t & 31) == 0) { smin[t >> 5] = lmin; smax[t >> 5] = lmax; }
    __syncthreads();
    if (t < 32) {
        lmin = (t < 8) ? smin[t] :  3.402823466e38f;
        lmax = (t < 8) ? smax[t] : -3.402823466e38f;
#pragma unroll
        for (int o = 4; o > 0; o >>= 1) {
            lmin = fminf(lmin, __shfl_xor_sync(0xFFFFFFFFu, lmin, o));
            lmax = fmaxf(lmax, __shfl_xor_sync(0xFFFFFFFFu, lmax, o));
        }
        if (t == 0) {
            atomicMin(&g_minb, f2o(lmin));
            atomicMax(&g_maxb, f2o(lmax));
        }
    }
}

// ---------------------------------------------------------------------------
// Kernel 3: in-place min-max normalize of d_out.
// ---------------------------------------------------------------------------
__global__ void __launch_bounds__(256) k_norm(float4* __restrict__ out)
{
    int i = blockIdx.x * 256 + threadIdx.x;     // 0 .. OD*HW4-1
    float mn = o2f(g_minb);
    float mx = o2f(g_maxb);
    float inv = 1.0f / (mx - mn);
    float4 v = out[i];
    v.x = (v.x - mn) * inv;
    v.y = (v.y - mn) * inv;
    v.z = (v.z - mn) * inv;
    v.w = (v.w - mn) * inv;
    out[i] = v;
}

extern "C" void kernel_launch(void* const* d_in, const int* in_sizes, int n_in,
                              void* d_out, int out_size)
{
    const float* inp  = (const float*)d_in[0];
    const float* mu_z = (const float*)d_in[1];
    const float* sigz = (const float*)d_in[2];
    const float* bxy  = (const float*)d_in[3];
    const float* bz   = (const float*)d_in[4];
    float* out = (float*)d_out;

    k_init<<<1, 1>>>();

    dim3 g1(HW4 / 256, OD / 8);       // (256, 4)
    k_zconv<<<g1, 256>>>((const float4*)inp, mu_z, sigz, bz);

    dim3 g2(Ww / 32, Hh / 32, OD);    // (16, 16, 32)
    k_xyconv<<<g2, 256>>>(bxy, out);

    int n4 = OD * HW4;                // 8,388,608/4
    k_norm<<<n4 / 256, 256>>>((float4*)out);
}

// round 2
// speedup vs baseline: 1.0510x; 1.0510x over previous
#include <cuda_runtime.h>
#include <math.h>

#define Dd 128
#define Hh 512
#define Ww 512
#define OD 32
#define HW (Hh*Ww)
#define HW4 (HW/4)
#define INV_SQRT_2PI 0.3989422804014327f

// scratch: z-conv output (32,512,512) f32 = 33.5 MB
__device__ __align__(16) float g_tmp1[(size_t)OD * HW];
__device__ unsigned g_minb;
__device__ unsigned g_maxb;

// float -> order-preserving uint (monotone), and inverse
__device__ __forceinline__ unsigned f2o(float f) {
    unsigned u = __float_as_uint(f);
    return (u & 0x80000000u) ? ~u : (u | 0x80000000u);
}
__device__ __forceinline__ float o2f(unsigned u) {
    return (u & 0x80000000u) ? __uint_as_float(u ^ 0x80000000u)
                             : __uint_as_float(~u);
}

// ---------------------------------------------------------------------------
// Kernel 1: strided z-conv.  Each thread: one float4 (x,y) group, 16
// consecutive output z-planes.  Reads 69 input planes (1.08x redundancy).
// out[zo] = sum_{kz=0..8} wz[kz] * in[4*zo - 3 + kz]
// Also resets the global min/max accumulators (ordered before k_xyconv).
// ---------------------------------------------------------------------------
__global__ void __launch_bounds__(256) k_zconv(
    const float4* __restrict__ in,
    const float* __restrict__ p_mu, const float* __restrict__ p_sig,
    const float* __restrict__ p_bz)
{
    if (blockIdx.x == 0 && blockIdx.y == 0 && threadIdx.x == 0) {
        g_minb = 0xFFFFFFFFu;
        g_maxb = 0u;
    }

    int idx = blockIdx.x * 256 + threadIdx.x;   // 0 .. HW4-1
    int zb  = blockIdx.y * 16;                  // first output z of this chunk

    float bz  = *p_bz;
    float z0  = expf(*p_mu + 0.5f * (*p_sig) * (*p_sig));
    float amp = INV_SQRT_2PI * z0;
    float inv2b2 = 1.0f / (2.0f * bz * bz);

    float wz[9];
#pragma unroll
    for (int k = 0; k < 9; k++) {
        float d = (float)(k - 4);
        wz[k] = expf(-d * d * inv2b2) * amp;
    }

    float4 acc[16];
#pragma unroll
    for (int j = 0; j < 16; j++) acc[j] = make_float4(0.f, 0.f, 0.f, 0.f);

    int base = 4 * zb - 3;                      // input z of iz=0
    // planes needed: base .. base + 4*15 + 8 = base + 68  -> 69 planes
#pragma unroll
    for (int iz = 0; iz < 69; iz++) {
        int z = base + iz;
        float4 v;
        if (z >= 0 && z < Dd) v = in[(size_t)z * HW4 + idx];
        else                  v = make_float4(0.f, 0.f, 0.f, 0.f);
#pragma unroll
        for (int j = 0; j < 16; j++) {
            int kz = iz - 4 * j;                // compile-time per (iz,j)
            if (kz >= 0 && kz < 9) {
                float w = wz[kz];
                acc[j].x += w * v.x;
                acc[j].y += w * v.y;
                acc[j].z += w * v.z;
                acc[j].w += w * v.w;
            }
        }
    }

    float4* out = reinterpret_cast<float4*>(g_tmp1);
#pragma unroll
    for (int j = 0; j < 16; j++)
        out[(size_t)(zb + j) * HW4 + idx] = acc[j];
}

// ---------------------------------------------------------------------------
// Kernel 2: fused x-conv + y-conv, register sliding-window separable conv.
// Tile: 32 rows (x) x 64 cols (y); halo 40 x 72.  Fused global min/max.
//   Phase B (y-conv): 160 threads, each owns (row, 16-col segment):
//     loads 24 consecutive values once, emits 16 outputs.
//   Phase C (x-conv): 256 threads, each owns (col, 8-row segment):
//     loads 16 column values once, emits 8 outputs.
// LDS traffic ~3x lower than naive tap loops.
// ---------------------------------------------------------------------------
__global__ void __launch_bounds__(256) k_xyconv(
    const float* __restrict__ p_bxy, float* __restrict__ out)
{
    __shared__ float s_in[40 * 72];
    __shared__ float s_tmp[40 * 64];
    __shared__ float smin[8], smax[8];

    int z  = blockIdx.z;
    int X0 = blockIdx.y * 32;
    int Y0 = blockIdx.x * 64;
    int t  = threadIdx.x;

    float bxy = *p_bxy;
    float inv2b2 = 1.0f / (2.0f * bxy * bxy);
    float w[9];
#pragma unroll
    for (int k = 0; k < 9; k++) {
        float d = (float)(k - 4);
        w[k] = expf(-d * d * inv2b2);
    }

    const float* src = g_tmp1 + (size_t)z * HW;

    // ---- Phase A: load 40x72 halo (zero padded), coalesced ----
    for (int i = t; i < 40 * 72; i += 256) {
        int r = i / 72, c = i % 72;
        int gx = X0 - 4 + r, gy = Y0 - 4 + c;
        s_in[i] = (gx >= 0 && gx < Hh && gy >= 0 && gy < Ww)
                      ? src[(size_t)gx * Ww + gy] : 0.f;
    }
    __syncthreads();

    // ---- Phase B: y-conv with register sliding window ----
    if (t < 160) {
        int row = t >> 2;             // 0..39
        int c0  = (t & 3) * 16;       // 0,16,32,48
        float v[24];
#pragma unroll
        for (int i = 0; i < 24; i++) v[i] = s_in[row * 72 + c0 + i];
#pragma unroll
        for (int o = 0; o < 16; o++) {
            float s = 0.f;
#pragma unroll
            for (int k = 0; k < 9; k++) s += w[k] * v[o + k];
            s_tmp[row * 64 + c0 + o] = s;
        }
    }
    __syncthreads();

    // ---- Phase C: x-conv with register sliding window, fused min/max ----
    int col = t & 63;                 // 0..63
    int x0  = (t >> 6) * 8;           // 0,8,16,24
    float v[16];
#pragma unroll
    for (int i = 0; i < 16; i++) v[i] = s_tmp[(x0 + i) * 64 + col];

    float lmin =  3.402823466e38f;
    float lmax = -3.402823466e38f;
    float* dst = out + (size_t)z * HW + (size_t)(X0 + x0) * Ww + (Y0 + col);
#pragma unroll
    for (int o = 0; o < 8; o++) {
        float s = 0.f;
#pragma unroll
        for (int k = 0; k < 9; k++) s += w[k] * v[o + k];
        dst[(size_t)o * Ww] = s;
        lmin = fminf(lmin, s);
        lmax = fmaxf(lmax, s);
    }

    // block reduce min/max
#pragma unroll
    for (int o = 16; o > 0; o >>= 1) {
        lmin = fminf(lmin, __shfl_xor_sync(0xFFFFFFFFu, lmin, o));
        lmax = fmaxf(lmax, __shfl_xor_sync(0xFFFFFFFFu, lmax, o));
    }
    if ((t & 31) == 0) { smin[t >> 5] = lmin; smax[t >> 5] = lmax; }
    __syncthreads();
    if (t < 32) {
        lmin = (t < 8) ? smin[t] :  3.402823466e38f;
        lmax = (t < 8) ? smax[t] : -3.402823466e38f;
#pragma unroll
        for (int o = 4; o > 0; o >>= 1) {
            lmin = fminf(lmin, __shfl_xor_sync(0xFFFFFFFFu, lmin, o));
            lmax = fmaxf(lmax, __shfl_xor_sync(0xFFFFFFFFu, lmax, o));
        }
        if (t == 0) {
            atomicMin(&g_minb, f2o(lmin));
            atomicMax(&g_maxb, f2o(lmax));
        }
    }
}

// ---------------------------------------------------------------------------
// Kernel 3: in-place min-max normalize of d_out (largely L2-resident).
// ---------------------------------------------------------------------------
__global__ void __launch_bounds__(256) k_norm(float4* __restrict__ out)
{
    int i = blockIdx.x * 256 + threadIdx.x;     // 0 .. OD*HW4-1
    float mn = o2f(g_minb);
    float mx = o2f(g_maxb);
    float inv = 1.0f / (mx - mn);
    float4 v = out[i];
    v.x = (v.x - mn) * inv;
    v.y = (v.y - mn) * inv;
    v.z = (v.z - mn) * inv;
    v.w = (v.w - mn) * inv;
    out[i] = v;
}

extern "C" void kernel_launch(void* const* d_in, const int* in_sizes, int n_in,
                              void* d_out, int out_size)
{
    const float* inp  = (const float*)d_in[0];
    const float* mu_z = (const float*)d_in[1];
    const float* sigz = (const float*)d_in[2];
    const float* bxy  = (const float*)d_in[3];
    const float* bz   = (const float*)d_in[4];
    float* out = (float*)d_out;

    dim3 g1(HW4 / 256, OD / 16);      // (256, 2)
    k_zconv<<<g1, 256>>>((const float4*)inp, mu_z, sigz, bz);

    dim3 g2(Ww / 64, Hh / 32, OD);    // (8, 16, 32)
    k_xyconv<<<g2, 256>>>(bxy, out);

    int n4 = OD * HW4;
    k_norm<<<n4 / 256, 256>>>((float4*)out);
}

// round 3
// speedup vs baseline: 1.2824x; 1.2201x over previous
#include <cuda_runtime.h>
#include <math.h>

#define Dd 128
#define Hh 512
#define Ww 512
#define OD 32
#define HW (Hh*Ww)
#define HW4 (HW/4)
#define INV_SQRT_2PI 0.3989422804014327f

// scratch: z-conv output (32,512,512) f32 = 33.5 MB
__device__ __align__(16) float g_tmp1[(size_t)OD * HW];
__device__ unsigned g_minb;
__device__ unsigned g_maxb;

// float -> order-preserving uint (monotone), and inverse
__device__ __forceinline__ unsigned f2o(float f) {
    unsigned u = __float_as_uint(f);
    return (u & 0x80000000u) ? ~u : (u | 0x80000000u);
}
__device__ __forceinline__ float o2f(unsigned u) {
    return (u & 0x80000000u) ? __uint_as_float(u ^ 0x80000000u)
                             : __uint_as_float(~u);
}

// ---------------------------------------------------------------------------
// Kernel 1: strided z-conv.  8 outputs/thread, 4-deep register prefetch ring.
// Reads 37 input planes per 8 outputs (1.16x), streamed with __ldcs so the
// scratch writes stay L2-resident for k_xyconv.
// out[zo] = sum_{kz=0..8} wz[kz] * in[4*zo - 3 + kz]
// ---------------------------------------------------------------------------
#define ZPF 4
__global__ void __launch_bounds__(256) k_zconv(
    const float4* __restrict__ in,
    const float* __restrict__ p_mu, const float* __restrict__ p_sig,
    const float* __restrict__ p_bz)
{
    if (blockIdx.x == 0 && blockIdx.y == 0 && threadIdx.x == 0) {
        g_minb = 0xFFFFFFFFu;
        g_maxb = 0u;
    }

    int idx = blockIdx.x * 256 + threadIdx.x;   // 0 .. HW4-1
    int zb  = blockIdx.y * 8;                   // first output z of this chunk

    float bz  = *p_bz;
    float z0  = expf(*p_mu + 0.5f * (*p_sig) * (*p_sig));
    float amp = INV_SQRT_2PI * z0;
    float inv2b2 = 1.0f / (2.0f * bz * bz);

    float wz[9];
#pragma unroll
    for (int k = 0; k < 9; k++) {
        float d = (float)(k - 4);
        wz[k] = expf(-d * d * inv2b2) * amp;
    }

    float4 acc[8];
#pragma unroll
    for (int j = 0; j < 8; j++) acc[j] = make_float4(0.f, 0.f, 0.f, 0.f);

    const int base = 4 * zb - 3;                // input z of iz=0 (37 planes)
    const float4* p = in + idx;

    // prefetch ring
    float4 buf[ZPF];
#pragma unroll
    for (int i = 0; i < ZPF; i++) {
        int z = base + i;
        buf[i] = (z >= 0 && z < Dd) ? __ldcs(p + (size_t)z * HW4)
                                    : make_float4(0.f, 0.f, 0.f, 0.f);
    }

#pragma unroll
    for (int iz = 0; iz < 37; iz++) {
        float4 v = buf[iz % ZPF];
        int nz = iz + ZPF;
        if (nz < 37) {                          // compile-time (full unroll)
            int z = base + nz;
            buf[iz % ZPF] = (z >= 0 && z < Dd)
                                ? __ldcs(p + (size_t)z * HW4)
                                : make_float4(0.f, 0.f, 0.f, 0.f);
        }
#pragma unroll
        for (int j = 0; j < 8; j++) {
            int kz = iz - 4 * j;                // compile-time per (iz,j)
            if (kz >= 0 && kz < 9) {
                float w = wz[kz];
                acc[j].x += w * v.x;
                acc[j].y += w * v.y;
                acc[j].z += w * v.z;
                acc[j].w += w * v.w;
            }
        }
    }

    float4* out = reinterpret_cast<float4*>(g_tmp1);
#pragma unroll
    for (int j = 0; j < 8; j++)
        out[(size_t)(zb + j) * HW4 + idx] = acc[j];
}

// ---------------------------------------------------------------------------
// Kernel 2: fused x-conv + y-conv, 64x64 tile (72x72 halo), padded smem
// strides (73 / 65) to kill the 8-way bank conflicts, register sliding
// windows (24 in -> 16 out per thread), fused global min/max.
// ---------------------------------------------------------------------------
#define SIN 73
#define STM 65
__global__ void __launch_bounds__(256) k_xyconv(
    const float* __restrict__ p_bxy, float* __restrict__ out)
{
    __shared__ float s_in[72 * SIN];
    __shared__ float s_tmp[72 * STM];
    __shared__ float smin[8], smax[8];

    int z  = blockIdx.z;
    int X0 = blockIdx.y * 64;
    int Y0 = blockIdx.x * 64;
    int t  = threadIdx.x;

    float bxy = *p_bxy;
    float inv2b2 = 1.0f / (2.0f * bxy * bxy);
    float w[9];
#pragma unroll
    for (int k = 0; k < 9; k++) {
        float d = (float)(k - 4);
        w[k] = expf(-d * d * inv2b2);
    }

    const float* src = g_tmp1 + (size_t)z * HW;

    // ---- Phase A: load 72x72 halo (zero padded), coalesced ----
    for (int i = t; i < 72 * 72; i += 256) {
        int r = i / 72, c = i % 72;
        int gx = X0 - 4 + r, gy = Y0 - 4 + c;
        s_in[r * SIN + c] = (gx >= 0 && gx < Hh && gy >= 0 && gy < Ww)
                                ? src[(size_t)gx * Ww + gy] : 0.f;
    }
    __syncthreads();

    // ---- Phase B: y-conv, register sliding window (72 rows x 4 segs) ----
    for (int u = t; u < 288; u += 256) {
        int row = u >> 2;             // 0..71
        int c0  = (u & 3) * 16;       // 0,16,32,48
        float v[24];
#pragma unroll
        for (int i = 0; i < 24; i++) v[i] = s_in[row * SIN + c0 + i];
#pragma unroll
        for (int o = 0; o < 16; o++) {
            float s = 0.f;
#pragma unroll
            for (int k = 0; k < 9; k++) s += w[k] * v[o + k];
            s_tmp[row * STM + c0 + o] = s;
        }
    }
    __syncthreads();

    // ---- Phase C: x-conv, register sliding window, fused min/max ----
    int col = t & 63;                 // 0..63
    int x0  = (t >> 6) * 16;          // 0,16,32,48
    float v[24];
#pragma unroll
    for (int i = 0; i < 24; i++) v[i] = s_tmp[(x0 + i) * STM + col];

    float lmin =  3.402823466e38f;
    float lmax = -3.402823466e38f;
    float* dst = out + (size_t)z * HW + (size_t)(X0 + x0) * Ww + (Y0 + col);
#pragma unroll
    for (int o = 0; o < 16; o++) {
        float s = 0.f;
#pragma unroll
        for (int k = 0; k < 9; k++) s += w[k] * v[o + k];
        dst[(size_t)o * Ww] = s;
        lmin = fminf(lmin, s);
        lmax = fmaxf(lmax, s);
    }

    // block reduce min/max
#pragma unroll
    for (int o = 16; o > 0; o >>= 1) {
        lmin = fminf(lmin, __shfl_xor_sync(0xFFFFFFFFu, lmin, o));
        lmax = fmaxf(lmax, __shfl_xor_sync(0xFFFFFFFFu, lmax, o));
    }
    if ((t & 31) == 0) { smin[t >> 5] = lmin; smax[t >> 5] = lmax; }
    __syncthreads();
    if (t < 32) {
        lmin = (t < 8) ? smin[t] :  3.402823466e38f;
        lmax = (t < 8) ? smax[t] : -3.402823466e38f;
#pragma unroll
        for (int o = 4; o > 0; o >>= 1) {
            lmin = fminf(lmin, __shfl_xor_sync(0xFFFFFFFFu, lmin, o));
            lmax = fmaxf(lmax, __shfl_xor_sync(0xFFFFFFFFu, lmax, o));
        }
        if (t == 0) {
            atomicMin(&g_minb, f2o(lmin));
            atomicMax(&g_maxb, f2o(lmax));
        }
    }
}

// ---------------------------------------------------------------------------
// Kernel 3: in-place min-max normalize of d_out (largely L2-resident).
// ---------------------------------------------------------------------------
__global__ void __launch_bounds__(256) k_norm(float4* __restrict__ out)
{
    int i = blockIdx.x * 256 + threadIdx.x;     // 0 .. OD*HW4-1
    float mn = o2f(g_minb);
    float mx = o2f(g_maxb);
    float inv = 1.0f / (mx - mn);
    float4 v = out[i];
    v.x = (v.x - mn) * inv;
    v.y = (v.y - mn) * inv;
    v.z = (v.z - mn) * inv;
    v.w = (v.w - mn) * inv;
    out[i] = v;
}

extern "C" void kernel_launch(void* const* d_in, const int* in_sizes, int n_in,
                              void* d_out, int out_size)
{
    const float* inp  = (const float*)d_in[0];
    const float* mu_z = (const float*)d_in[1];
    const float* sigz = (const float*)d_in[2];
    const float* bxy  = (const float*)d_in[3];
    const float* bz   = (const float*)d_in[4];
    float* out = (float*)d_out;

    dim3 g1(HW4 / 256, OD / 8);       // (256, 4) = 1024 blocks
    k_zconv<<<g1, 256>>>((const float4*)inp, mu_z, sigz, bz);

    dim3 g2(Ww / 64, Hh / 64, OD);    // (8, 8, 32) = 2048 blocks
    k_xyconv<<<g2, 256>>>(bxy, out);

    int n4 = OD * HW4;
    k_norm<<<n4 / 256, 256>>>((float4*)out);
}

// round 4
// speedup vs baseline: 1.4258x; 1.1118x over previous
#include <cuda_runtime.h>
#include <math.h>

#define Dd 128
#define Hh 512
#define Ww 512
#define OD 32
#define HW (Hh*Ww)
#define HW4 (HW/4)
#define INV_SQRT_2PI 0.3989422804014327f

// scratch: z-conv output (32,512,512) f32 = 33.5 MB
__device__ __align__(16) float g_tmp1[(size_t)OD * HW];
__device__ unsigned g_minb;
__device__ unsigned g_maxb;

// float -> order-preserving uint (monotone), and inverse
__device__ __forceinline__ unsigned f2o(float f) {
    unsigned u = __float_as_uint(f);
    return (u & 0x80000000u) ? ~u : (u | 0x80000000u);
}
__device__ __forceinline__ float o2f(unsigned u) {
    return (u & 0x80000000u) ? __uint_as_float(u ^ 0x80000000u)
                             : __uint_as_float(~u);
}

// ---------------------------------------------------------------------------
// Kernel 1: strided z-conv, cp.async double-buffered smem staging.
// Each thread stages ITS OWN column's planes (4 per chunk) into smem and
// consumes only its own slots -> no __syncthreads needed at all; ordering is
// purely cp.async.wait_group.  10 chunks cover iz = 0..36 (37 planes) for
// 8 z-outputs per thread (1.16x read redundancy).
// out[zo] = sum_{kz=0..8} wz[kz] * in[4*zo - 3 + kz]
// ---------------------------------------------------------------------------
__global__ void __launch_bounds__(256) k_zconv(
    const float4* __restrict__ in,
    const float* __restrict__ p_mu, const float* __restrict__ p_sig,
    const float* __restrict__ p_bz)
{
    __shared__ float4 sb[2][4][256];

    int t = threadIdx.x;
    if (blockIdx.x == 0 && blockIdx.y == 0 && t == 0) {
        g_minb = 0xFFFFFFFFu;
        g_maxb = 0u;
    }

    int idx = blockIdx.x * 256 + t;             // 0 .. HW4-1
    int zb  = blockIdx.y * 8;                   // first output z
    int base = 4 * zb - 3;                      // input z at iz=0
    const float4* p0 = in + idx;

    float bz  = *p_bz;
    float z0  = expf(*p_mu + 0.5f * (*p_sig) * (*p_sig));
    float amp = INV_SQRT_2PI * z0;
    float inv2b2 = 1.0f / (2.0f * bz * bz);

    float wz[9];
#pragma unroll
    for (int k = 0; k < 9; k++) {
        float d = (float)(k - 4);
        wz[k] = expf(-d * d * inv2b2) * amp;
    }

    float4 acc[8];
#pragma unroll
    for (int j = 0; j < 8; j++) acc[j] = make_float4(0.f, 0.f, 0.f, 0.f);

    // stage chunk c (planes iz = 4c .. 4c+3) into buffer c&1
#define ISSUE(c) do {                                                        \
        int st_ = (c) & 1;                                                   \
        _Pragma("unroll")                                                    \
        for (int q_ = 0; q_ < 4; q_++) {                                     \
            int iz_ = 4 * (c) + q_;                                          \
            int z_  = base + iz_;                                            \
            int ok_ = (z_ >= 0 && z_ < Dd && iz_ <= 36) ? 16 : 0;            \
            int zc_ = z_ < 0 ? 0 : (z_ >= Dd ? Dd - 1 : z_);                 \
            unsigned sa_ = (unsigned)__cvta_generic_to_shared(               \
                &sb[st_][q_][t]);                                            \
            const float4* g_ = p0 + (size_t)zc_ * HW4;                       \
            asm volatile(                                                    \
                "cp.async.cg.shared.global [%0], [%1], 16, %2;"              \
                :: "r"(sa_), "l"(g_), "r"(ok_) : "memory");                  \
        }                                                                    \
        asm volatile("cp.async.commit_group;" ::: "memory");                 \
    } while (0)

    ISSUE(0);
#pragma unroll
    for (int c = 0; c < 10; c++) {
        if (c < 9) {
            ISSUE(c + 1);
            asm volatile("cp.async.wait_group 1;" ::: "memory");
        } else {
            asm volatile("cp.async.wait_group 0;" ::: "memory");
        }
#pragma unroll
        for (int q = 0; q < 4; q++) {
            int iz = 4 * c + q;
            if (iz <= 36) {
                float4 v = sb[c & 1][q][t];
                // taps landing on this plane:  j=c (kz=q), j=c-1 (kz=4+q),
                // j=c-2 (kz=8, only q=0);  all indices compile-time.
                if (c < 8) {
                    float w = wz[q];
                    acc[c].x += w * v.x; acc[c].y += w * v.y;
                    acc[c].z += w * v.z; acc[c].w += w * v.w;
                }
                if (c >= 1 && c <= 8) {
                    float w = wz[4 + q];
                    acc[c-1].x += w * v.x; acc[c-1].y += w * v.y;
                    acc[c-1].z += w * v.z; acc[c-1].w += w * v.w;
                }
                if (q == 0 && c >= 2) {
                    float w = wz[8];
                    acc[c-2].x += w * v.x; acc[c-2].y += w * v.y;
                    acc[c-2].z += w * v.z; acc[c-2].w += w * v.w;
                }
            }
        }
    }
#undef ISSUE

    float4* out = reinterpret_cast<float4*>(g_tmp1);
#pragma unroll
    for (int j = 0; j < 8; j++)
        out[(size_t)(zb + j) * HW4 + idx] = acc[j];
}

// ---------------------------------------------------------------------------
// Kernel 2: fused x-conv + y-conv, 64x64 tile (72x72 halo), SINGLE in-place
// smem buffer (21 KB), padded stride 73, register sliding windows
// (24 in -> 16 out per thread), fused global min/max.  288 threads.
// ---------------------------------------------------------------------------
#define SIN 73
__global__ void __launch_bounds__(288) k_xyconv(
    const float* __restrict__ p_bxy, float* __restrict__ out)
{
    __shared__ float s_in[72 * SIN];
    __shared__ float smin[16], smax[16];

    int z  = blockIdx.z;
    int X0 = blockIdx.y * 64;
    int Y0 = blockIdx.x * 64;
    int t  = threadIdx.x;

    float bxy = *p_bxy;
    float inv2b2 = 1.0f / (2.0f * bxy * bxy);
    float w[9];
#pragma unroll
    for (int k = 0; k < 9; k++) {
        float d = (float)(k - 4);
        w[k] = expf(-d * d * inv2b2);
    }

    const float* src = g_tmp1 + (size_t)z * HW;

    // ---- Phase A: load 72x72 halo (zero padded), coalesced ----
#pragma unroll
    for (int it = 0; it < 18; it++) {            // 72*72 / 288 = 18
        int i = it * 288 + t;
        int r = i / 72, c = i % 72;
        int gx = X0 - 4 + r, gy = Y0 - 4 + c;
        s_in[r * SIN + c] = (gx >= 0 && gx < Hh && gy >= 0 && gy < Ww)
                                ? src[(size_t)gx * Ww + gy] : 0.f;
    }
    __syncthreads();

    // ---- Phase B: y-conv, in-place.  72 rows x 4 segs = 288 items. ----
    {
        int row = t >> 2;             // 0..71
        int c0  = (t & 3) * 16;       // 0,16,32,48
        float v[24];
#pragma unroll
        for (int i = 0; i < 24; i++) v[i] = s_in[row * SIN + c0 + i];
        __syncthreads();              // all windows loaded before overwrite
#pragma unroll
        for (int o = 0; o < 16; o++) {
            float s = 0.f;
#pragma unroll
            for (int k = 0; k < 9; k++) s += w[k] * v[o + k];
            s_in[row * SIN + c0 + o] = s;
        }
    }
    __syncthreads();

    // ---- Phase C: x-conv, register sliding window, fused min/max ----
    float lmin =  3.402823466e38f;
    float lmax = -3.402823466e38f;
    if (t < 256) {
        int col = t & 63;                 // 0..63
        int x0  = (t >> 6) * 16;          // 0,16,32,48
        float v[24];
#pragma unroll
        for (int i = 0; i < 24; i++) v[i] = s_in[(x0 + i) * SIN + col];

        float* dst = out + (size_t)z * HW + (size_t)(X0 + x0) * Ww + (Y0 + col);
#pragma unroll
        for (int o = 0; o < 16; o++) {
            float s = 0.f;
#pragma unroll
            for (int k = 0; k < 9; k++) s += w[k] * v[o + k];
            dst[(size_t)o * Ww] = s;
            lmin = fminf(lmin, s);
            lmax = fmaxf(lmax, s);
        }
    }

    // block reduce min/max (9 warps)
#pragma unroll
    for (int o = 16; o > 0; o >>= 1) {
        lmin = fminf(lmin, __shfl_xor_sync(0xFFFFFFFFu, lmin, o));
        lmax = fmaxf(lmax, __shfl_xor_sync(0xFFFFFFFFu, lmax, o));
    }
    if ((t & 31) == 0) { smin[t >> 5] = lmin; smax[t >> 5] = lmax; }
    __syncthreads();
    if (t < 16) {
        lmin = (t < 9) ? smin[t] :  3.402823466e38f;
        lmax = (t < 9) ? smax[t] : -3.402823466e38f;
#pragma unroll
        for (int o = 8; o > 0; o >>= 1) {
            lmin = fminf(lmin, __shfl_xor_sync(0x0000FFFFu, lmin, o));
            lmax = fmaxf(lmax, __shfl_xor_sync(0x0000FFFFu, lmax, o));
        }
        if (t == 0) {
            atomicMin(&g_minb, f2o(lmin));
            atomicMax(&g_maxb, f2o(lmax));
        }
    }
}

// ---------------------------------------------------------------------------
// Kernel 3: in-place min-max normalize of d_out, 2 float4 per thread.
// ---------------------------------------------------------------------------
__global__ void __launch_bounds__(256) k_norm(float4* __restrict__ out)
{
    int i = blockIdx.x * 512 + threadIdx.x;
    float mn = o2f(g_minb);
    float mx = o2f(g_maxb);
    float inv = 1.0f / (mx - mn);
    float4 a = out[i];
    float4 b = out[i + 256];
    a.x = (a.x - mn) * inv; a.y = (a.y - mn) * inv;
    a.z = (a.z - mn) * inv; a.w = (a.w - mn) * inv;
    b.x = (b.x - mn) * inv; b.y = (b.y - mn) * inv;
    b.z = (b.z - mn) * inv; b.w = (b.w - mn) * inv;
    out[i] = a;
    out[i + 256] = b;
}

extern "C" void kernel_launch(void* const* d_in, const int* in_sizes, int n_in,
                              void* d_out, int out_size)
{
    const float* inp  = (const float*)d_in[0];
    const float* mu_z = (const float*)d_in[1];
    const float* sigz = (const float*)d_in[2];
    const float* bxy  = (const float*)d_in[3];
    const float* bz   = (const float*)d_in[4];
    float* out = (float*)d_out;

    dim3 g1(HW4 / 256, OD / 8);       // (256, 4) = 1024 blocks
    k_zconv<<<g1, 256>>>((const float4*)inp, mu_z, sigz, bz);

    dim3 g2(Ww / 64, Hh / 64, OD);    // (8, 8, 32) = 2048 blocks
    k_xyconv<<<g2, 288>>>(bxy, out);

    int n4 = OD * HW4;                // 2,097,152 float4s
    k_norm<<<n4 / 512, 256>>>((float4*)out);
}